// round 12
// baseline (speedup 1.0000x reference)
#include <cuda_runtime.h>
#include <cuda_fp16.h>
#include <cstdint>

#define BB 2
#define HH 8
#define DH 64
#define DM 512
#define NQ 4096
#define NK 4096

// -------- scratch (no allocations allowed) --------
__device__ __half g_qh[BB*HH*NQ*DH];
__device__ __half g_kh[BB*HH*NK*DH];
__device__ __half g_vh[BB*HH*NK*DH];
__device__ float  g_o [BB*HH*NQ*DH];           // UNNORMALIZED O (E @ V)
__device__ float  g_zi[BB*HH*NQ];              // 1 / rowsum(exp(S))
__device__ __half g_eh[(size_t)BB*HH*NQ*NK];   // unnormalized E, fp16
__device__ unsigned char g_mflags[BB*64*32];   // per-(b,qtile,ktile) mask flag

__device__ __forceinline__ float to_tf32(float x) {
    float r;
    asm("cvt.rna.tf32.f32 %0, %1;" : "=f"(r) : "f"(x));
    return r;
}
__device__ __forceinline__ float ex2f(float x) {
    float r;
    asm("ex2.approx.f32 %0, %1;" : "=f"(r) : "f"(x));
    return r;
}
// pack (lo, hi) floats -> f16x2 word, single CVT instr
__device__ __forceinline__ uint32_t cvt_h2(float lo, float hi) {
    uint32_t r;
    asm("cvt.rn.f16x2.f32 %0, %1, %2;" : "=r"(r) : "f"(hi), "f"(lo));
    return r;
}

// tf32: D += A(16x8) * B(8x8)
__device__ __forceinline__ void mma8(float* d, const float* a, const float* b) {
    asm("mma.sync.aligned.m16n8k8.row.col.f32.tf32.tf32.f32 "
        "{%0,%1,%2,%3}, {%4,%5,%6,%7}, {%8,%9}, {%0,%1,%2,%3};"
        : "+f"(d[0]), "+f"(d[1]), "+f"(d[2]), "+f"(d[3])
        : "r"(__float_as_uint(a[0])), "r"(__float_as_uint(a[1])),
          "r"(__float_as_uint(a[2])), "r"(__float_as_uint(a[3])),
          "r"(__float_as_uint(b[0])), "r"(__float_as_uint(b[1])));
}

// fp16: D(16x8,f32) += A(16x16) * B(16x8)
__device__ __forceinline__ void mma16(float* d, const uint32_t* a, const uint32_t* b) {
    asm("mma.sync.aligned.m16n8k16.row.col.f32.f16.f16.f32 "
        "{%0,%1,%2,%3}, {%4,%5,%6,%7}, {%8,%9}, {%0,%1,%2,%3};"
        : "+f"(d[0]), "+f"(d[1]), "+f"(d[2]), "+f"(d[3])
        : "r"(a[0]), "r"(a[1]), "r"(a[2]), "r"(a[3]),
          "r"(b[0]), "r"(b[1]));
}

__device__ __forceinline__ void ldsm_x4(uint32_t* r, uint32_t addr) {
    asm volatile("ldmatrix.sync.aligned.m8n8.x4.shared.b16 {%0,%1,%2,%3}, [%4];"
        : "=r"(r[0]), "=r"(r[1]), "=r"(r[2]), "=r"(r[3]) : "r"(addr));
}
__device__ __forceinline__ void ldsm_x4_t(uint32_t* r, uint32_t addr) {
    asm volatile("ldmatrix.sync.aligned.m8n8.x4.trans.shared.b16 {%0,%1,%2,%3}, [%4];"
        : "=r"(r[0]), "=r"(r[1]), "=r"(r[2]), "=r"(r[3]) : "r"(addr));
}

__device__ __forceinline__ void cpa16(uint32_t dst, const void* src) {
    asm volatile("cp.async.cg.shared.global [%0], [%1], 16;" :: "r"(dst), "l"(src));
}
__device__ __forceinline__ void cpa_commit() {
    asm volatile("cp.async.commit_group;" ::: "memory");
}
__device__ __forceinline__ void cpa_wait0() {
    asm volatile("cp.async.wait_group 0;" ::: "memory");
}

__device__ __forceinline__ uint32_t pack_h2(float x, float y) {
    __half2 h = __floats2half2_rn(x, y);
    return *(uint32_t*)&h;
}
__device__ __forceinline__ uint32_t smem_u32(const void* p) {
    return (uint32_t)__cvta_generic_to_shared(p);
}

// ============================================================
// Mask tile scan
// ============================================================
__global__ __launch_bounds__(256) void mask_scan_kernel(const unsigned char* __restrict__ mask)
{
    int bid = blockIdx.x;
    int b  = bid >> 11;
    int qt = (bid >> 5) & 63;
    int kt = bid & 31;
    const uint4* s = (const uint4*)(mask + (size_t)b * NQ * NK
                                    + (size_t)(qt * 64 + (threadIdx.x >> 2)) * NK
                                    + kt * 128 + (threadIdx.x & 3) * 32);
    uint4 a = s[0], c = s[1];
    unsigned v = a.x | a.y | a.z | a.w | c.x | c.y | c.z | c.w;
#pragma unroll
    for (int o = 16; o > 0; o >>= 1) v |= __shfl_xor_sync(0xffffffffu, v, o);
    __shared__ unsigned sflag;
    if (threadIdx.x == 0) sflag = 0u;
    __syncthreads();
    if ((threadIdx.x & 31) == 0 && v) atomicOr(&sflag, 1u);
    __syncthreads();
    if (threadIdx.x == 0) g_mflags[bid] = (unsigned char)(sflag != 0u);
}

// ============================================================
// Fused QKV projection (tf32), grid.z selects q/k/v. fp16 output.
// ============================================================
__global__ __launch_bounds__(256) void proj_qkv_kernel(
    const float* __restrict__ X0, const float* __restrict__ X1, const float* __restrict__ X2,
    const float* __restrict__ W0, const float* __restrict__ W1, const float* __restrict__ W2,
    const float* __restrict__ B0, const float* __restrict__ B1, const float* __restrict__ B2)
{
    int sel = blockIdx.z;
    const float* X = sel == 0 ? X0 : (sel == 1 ? X1 : X2);
    const float* W = sel == 0 ? W0 : (sel == 1 ? W1 : W2);
    const float* bias = sel == 0 ? B0 : (sel == 1 ? B1 : B2);
    __half* dst = sel == 0 ? g_qh : (sel == 1 ? g_kh : g_vh);

    __shared__ float As[128][36];
    __shared__ float Ws[64][36];
    int tid = threadIdx.x;
    int lane = tid & 31, warp = tid >> 5;
    int g = lane >> 2, t = lane & 3;
    int wm = warp >> 1, wn = warp & 1;
    int m0 = blockIdx.x * 128;
    int h  = blockIdx.y;

    float acc[2][4][4];
#pragma unroll
    for (int i = 0; i < 2; i++)
#pragma unroll
        for (int j = 0; j < 4; j++)
#pragma unroll
            for (int c = 0; c < 4; c++) acc[i][j][c] = 0.f;

    int rl = tid >> 3, cl = (tid & 7) * 4;
    for (int k0 = 0; k0 < DM; k0 += 32) {
#pragma unroll
        for (int i = 0; i < 4; i++) {
            int r = rl + i * 32;
            float4 v = *(const float4*)(X + (size_t)(m0 + r) * DM + k0 + cl);
            As[r][cl]   = to_tf32(v.x);
            As[r][cl+1] = to_tf32(v.y);
            As[r][cl+2] = to_tf32(v.z);
            As[r][cl+3] = to_tf32(v.w);
        }
#pragma unroll
        for (int i = 0; i < 2; i++) {
            int r = rl + i * 32;
            float4 v = *(const float4*)(W + (size_t)(h * 64 + r) * DM + k0 + cl);
            Ws[r][cl]   = to_tf32(v.x);
            Ws[r][cl+1] = to_tf32(v.y);
            Ws[r][cl+2] = to_tf32(v.z);
            Ws[r][cl+3] = to_tf32(v.w);
        }
        __syncthreads();
#pragma unroll
        for (int kk = 0; kk < 4; kk++) {
            float a[2][4];
#pragma unroll
            for (int mt = 0; mt < 2; mt++) {
                int rb = wm * 32 + mt * 16;
                a[mt][0] = As[rb + g][kk*8 + t];
                a[mt][1] = As[rb + 8 + g][kk*8 + t];
                a[mt][2] = As[rb + g][kk*8 + t + 4];
                a[mt][3] = As[rb + 8 + g][kk*8 + t + 4];
            }
            float bf[4][2];
#pragma unroll
            for (int nt = 0; nt < 4; nt++) {
                int nl = wn * 32 + nt * 8 + g;
                bf[nt][0] = Ws[nl][kk*8 + t];
                bf[nt][1] = Ws[nl][kk*8 + t + 4];
            }
#pragma unroll
            for (int mt = 0; mt < 2; mt++)
#pragma unroll
                for (int nt = 0; nt < 4; nt++)
                    mma8(acc[mt][nt], a[mt], bf[nt]);
        }
        __syncthreads();
    }
#pragma unroll
    for (int mt = 0; mt < 2; mt++) {
        int r0 = m0 + wm * 32 + mt * 16 + g;
        int r1 = r0 + 8;
#pragma unroll
        for (int nt = 0; nt < 4; nt++) {
            int col = wn * 32 + nt * 8 + 2 * t;
            float b0v = bias[h * 64 + col], b1v = bias[h * 64 + col + 1];
            int b_ = r0 >> 12, q_ = r0 & 4095;
            *(uint32_t*)(dst + (size_t)((b_ * HH + h) * NQ + q_) * DH + col) =
                pack_h2(acc[mt][nt][0] + b0v, acc[mt][nt][1] + b1v);
            b_ = r1 >> 12; q_ = r1 & 4095;
            *(uint32_t*)(dst + (size_t)((b_ * HH + h) * NQ + q_) * DH + col) =
                pack_h2(acc[mt][nt][2] + b0v, acc[mt][nt][3] + b1v);
        }
    }
}

// ============================================================
// Output projection (tf32)
// ============================================================
__global__ __launch_bounds__(256) void proj_out_kernel(
    const float* __restrict__ W, const float* __restrict__ bias,
    float* __restrict__ Y)
{
    __shared__ float As[128][36];
    __shared__ float Ws[64][36];
    int tid = threadIdx.x;
    int lane = tid & 31, warp = tid >> 5;
    int g = lane >> 2, t = lane & 3;
    int wm = warp >> 1, wn = warp & 1;
    int m0 = blockIdx.x * 128;
    int n0 = blockIdx.y * 64;

    float acc[2][4][4];
#pragma unroll
    for (int i = 0; i < 2; i++)
#pragma unroll
        for (int j = 0; j < 4; j++)
#pragma unroll
            for (int c = 0; c < 4; c++) acc[i][j][c] = 0.f;

    int rl = tid >> 3, cl = (tid & 7) * 4;
    for (int k0 = 0; k0 < DM; k0 += 32) {
        int head = k0 >> 6;
        int dd = (k0 & 63) + cl;
#pragma unroll
        for (int i = 0; i < 4; i++) {
            int r = rl + i * 32;
            int row = m0 + r;
            int b_ = row >> 12, q_ = row & 4095;
            size_t hb = (size_t)(b_ * HH + head) * NQ + q_;
            float zi = g_zi[hb];
            float4 v = *(const float4*)(g_o + hb * DH + dd);
            As[r][cl]   = to_tf32(v.x * zi);
            As[r][cl+1] = to_tf32(v.y * zi);
            As[r][cl+2] = to_tf32(v.z * zi);
            As[r][cl+3] = to_tf32(v.w * zi);
        }
#pragma unroll
        for (int i = 0; i < 2; i++) {
            int r = rl + i * 32;
            float4 v = *(const float4*)(W + (size_t)(n0 + r) * DM + k0 + cl);
            Ws[r][cl]   = to_tf32(v.x);
            Ws[r][cl+1] = to_tf32(v.y);
            Ws[r][cl+2] = to_tf32(v.z);
            Ws[r][cl+3] = to_tf32(v.w);
        }
        __syncthreads();
#pragma unroll
        for (int kk = 0; kk < 4; kk++) {
            float a[2][4];
#pragma unroll
            for (int mt = 0; mt < 2; mt++) {
                int rb = wm * 32 + mt * 16;
                a[mt][0] = As[rb + g][kk*8 + t];
                a[mt][1] = As[rb + 8 + g][kk*8 + t];
                a[mt][2] = As[rb + g][kk*8 + t + 4];
                a[mt][3] = As[rb + 8 + g][kk*8 + t + 4];
            }
            float bf[4][2];
#pragma unroll
            for (int nt = 0; nt < 4; nt++) {
                int nl = wn * 32 + nt * 8 + g;
                bf[nt][0] = Ws[nl][kk*8 + t];
                bf[nt][1] = Ws[nl][kk*8 + t + 4];
            }
#pragma unroll
            for (int mt = 0; mt < 2; mt++)
#pragma unroll
                for (int nt = 0; nt < 4; nt++)
                    mma8(acc[mt][nt], a[mt], bf[nt]);
        }
        __syncthreads();
    }
#pragma unroll
    for (int mt = 0; mt < 2; mt++) {
        int r0 = m0 + wm * 32 + mt * 16 + g;
        int r1 = r0 + 8;
#pragma unroll
        for (int nt = 0; nt < 4; nt++) {
            int col = wn * 32 + nt * 8 + 2 * t;
            float b0v = bias[n0 + col], b1v = bias[n0 + col + 1];
            float* p = Y + (size_t)r0 * DM + n0 + col;
            p[0] = acc[mt][nt][0] + b0v;
            p[1] = acc[mt][nt][1] + b1v;
            p = Y + (size_t)r1 * DM + n0 + col;
            p[0] = acc[mt][nt][2] + b0v;
            p[1] = acc[mt][nt][3] + b1v;
        }
    }
}

// ============================================================
// Attention: fp16 mma + ldmatrix + cp.async double-buffered K/V.
// (round-7 structure; ex2 + single-CVT exp path)
// ============================================================
#define QH_OFF   0                     // half [64][72]       =  9216
#define KH_OFF   9216                  // 2 x half [128][72]  = 36864
#define VH_OFF   46080                 // 2 x half [128][72]  = 36864
#define PH_OFF   82944                 // half [64][136]      = 17408 (also float Os[64][68])
#define ZS_OFF   100352                // float [64]
#define MS_OFF   100608                // u32 [64][32]        =  8192
#define SMEM_BYTES 108800

#define QROW 72
#define KROW 72
#define VROW 72
#define PROW 136
#define KBUF 18432
#define VBUF 18432

__global__ __launch_bounds__(256, 2) void attn_kernel(const unsigned char* __restrict__ mask)
{
    extern __shared__ char smraw[];
    __half* Qh = (__half*)(smraw + QH_OFF);
    __half* Ph = (__half*)(smraw + PH_OFF);
    float*  Zs = (float*)(smraw + ZS_OFF);
    unsigned int* Ms = (unsigned int*)(smraw + MS_OFF);
    uint32_t* Phw = (uint32_t*)Ph;

    int tid = threadIdx.x;
    int lane = tid & 31, warp = tid >> 5;
    int g = lane >> 2, t = lane & 3;
    int wm = warp >> 2;
    int wn = warp & 3;
    int q0 = blockIdx.x * 64;
    int bh = blockIdx.y;
    int b = bh >> 3, h = bh & 7;
    size_t headbase = (size_t)(b * HH + h) * NQ * DH;
    const unsigned char* mbase = mask + (size_t)(b * NQ + q0) * NK;
    int mfbase = b * 2048 + blockIdx.x * 32;
    int rbase = wm * 32;
    const float C = 0.18033688f;   // 0.125 * log2(e)

    uint32_t qbase = smem_u32(Qh);
    uint32_t kbase = smem_u32(smraw + KH_OFF);
    uint32_t vbase = smem_u32(smraw + VH_OFF);
    uint32_t pbase = smem_u32(Ph);

    // ---- prologue: cp.async Q tile + K/V tile 0 ----
    {
#pragma unroll
        for (int j = 0; j < 2; j++) {
            int idx = tid + j * 256;
            int r = idx >> 3, o = (idx & 7) * 8;
            cpa16(qbase + (r * QROW + o) * 2, g_qh + headbase + (size_t)(q0 + r) * DH + o);
        }
#pragma unroll
        for (int j = 0; j < 4; j++) {
            int idx = tid + j * 256;
            int r = idx >> 3, o = (idx & 7) * 8;
            cpa16(kbase + (r * KROW + o) * 2, g_kh + headbase + (size_t)r * DH + o);
            cpa16(vbase + (r * VROW + o) * 2, g_vh + headbase + (size_t)r * DH + o);
        }
        cpa_commit();
    }
    if (tid < 64) Zs[tid] = 0.f;
    cpa_wait0();
    __syncthreads();

    // ---- hoist Q A-fragments ----
    uint32_t qa[2][4][4];
    {
        int qrow = ((lane >> 3) & 1) * 8 + (lane & 7);
        int qcol = (lane >> 4) * 8;
#pragma unroll
        for (int mt = 0; mt < 2; mt++)
#pragma unroll
            for (int kk = 0; kk < 4; kk++)
                ldsm_x4(qa[mt][kk],
                        qbase + ((rbase + mt * 16 + qrow) * QROW + kk * 16 + qcol) * 2);
    }

    float oacc[2][2][4];
#pragma unroll
    for (int i = 0; i < 2; i++)
#pragma unroll
        for (int j = 0; j < 2; j++)
#pragma unroll
            for (int c = 0; c < 4; c++) oacc[i][j][c] = 0.f;

    for (int kt = 0; kt < NK / 128; kt++) {
        int buf = kt & 1;
        uint32_t kb = kbase + buf * KBUF;
        uint32_t vb = vbase + buf * VBUF;
        unsigned char mflag = g_mflags[mfbase + kt];

        // ---- prefetch next K/V tile ----
        if (kt + 1 < NK / 128) {
            int nbuf = buf ^ 1;
            const __half* ksrc = g_kh + headbase + (size_t)(kt + 1) * 128 * DH;
            const __half* vsrc = g_vh + headbase + (size_t)(kt + 1) * 128 * DH;
#pragma unroll
            for (int j = 0; j < 4; j++) {
                int idx = tid + j * 256;
                int r = idx >> 3, o = (idx & 7) * 8;
                cpa16(kbase + nbuf * KBUF + (r * KROW + o) * 2, ksrc + (size_t)r * DH + o);
                cpa16(vbase + nbuf * VBUF + (r * VROW + o) * 2, vsrc + (size_t)r * DH + o);
            }
            cpa_commit();
        }

        if (mflag) {
            int r = tid >> 2, cb = (tid & 3) * 8;
            const uint4* src = (const uint4*)(mbase + (size_t)r * NK + kt * 128 + cb * 4);
            uint4 m0 = src[0], m1 = src[1];
            *(uint4*)(Ms + r * 32 + cb)     = m0;
            *(uint4*)(Ms + r * 32 + cb + 4) = m1;
            __syncthreads();
        }

        // ---- S = Q K^T ----
        float sacc[2][4][4];
#pragma unroll
        for (int i = 0; i < 2; i++)
#pragma unroll
            for (int j = 0; j < 4; j++)
#pragma unroll
                for (int c = 0; c < 4; c++) sacc[i][j][c] = 0.f;
        {
            int kn = (lane >> 4) * 8 + (lane & 7);
            int kc = ((lane >> 3) & 1) * 8;
#pragma unroll
            for (int kk = 0; kk < 4; kk++) {
                uint32_t bf[4][2];
#pragma unroll
                for (int half_n = 0; half_n < 2; half_n++) {
                    uint32_t r4[4];
                    ldsm_x4(r4, kb + ((wn * 32 + half_n * 16 + kn) * KROW + kk * 16 + kc) * 2);
                    bf[half_n * 2][0]     = r4[0];
                    bf[half_n * 2][1]     = r4[1];
                    bf[half_n * 2 + 1][0] = r4[2];
                    bf[half_n * 2 + 1][1] = r4[3];
                }
#pragma unroll
                for (int mt = 0; mt < 2; mt++)
#pragma unroll
                    for (int nt = 0; nt < 4; nt++)
                        mma16(sacc[mt][nt], qa[mt][kk], bf[nt]);
            }
        }

        // ---- E = 2^(S*C); Z accumulate; stage fp16 ----
        float rsum[4] = {0.f, 0.f, 0.f, 0.f};
        if (!mflag) {
#pragma unroll
            for (int mt = 0; mt < 2; mt++) {
                int r0 = rbase + mt * 16 + g, r1 = r0 + 8;
#pragma unroll
                for (int nt = 0; nt < 4; nt++) {
                    int c0 = wn * 32 + nt * 8 + 2 * t;
                    float p00 = ex2f(sacc[mt][nt][0] * C);
                    float p01 = ex2f(sacc[mt][nt][1] * C);
                    float p10 = ex2f(sacc[mt][nt][2] * C);
                    float p11 = ex2f(sacc[mt][nt][3] * C);
                    rsum[mt*2]     += p00 + p01;
                    rsum[mt*2 + 1] += p10 + p11;
                    Phw[r0 * 68 + (c0 >> 1)] = cvt_h2(p00, p01);
                    Phw[r1 * 68 + (c0 >> 1)] = cvt_h2(p10, p11);
                }
            }
        } else {
            const unsigned char* Mb = (const unsigned char*)Ms;
#pragma unroll
            for (int mt = 0; mt < 2; mt++) {
                int r0 = rbase + mt * 16 + g, r1 = r0 + 8;
#pragma unroll
                for (int nt = 0; nt < 4; nt++) {
                    int c0 = wn * 32 + nt * 8 + 2 * t;
                    float p00 = Mb[r0*128 + c0]     ? 0.f : ex2f(sacc[mt][nt][0] * C);
                    float p01 = Mb[r0*128 + c0 + 1] ? 0.f : ex2f(sacc[mt][nt][1] * C);
                    float p10 = Mb[r1*128 + c0]     ? 0.f : ex2f(sacc[mt][nt][2] * C);
                    float p11 = Mb[r1*128 + c0 + 1] ? 0.f : ex2f(sacc[mt][nt][3] * C);
                    rsum[mt*2]     += p00 + p01;
                    rsum[mt*2 + 1] += p10 + p11;
                    Phw[r0 * 68 + (c0 >> 1)] = cvt_h2(p00, p01);
                    Phw[r1 * 68 + (c0 >> 1)] = cvt_h2(p10, p11);
                }
            }
        }
#pragma unroll
        for (int i = 0; i < 4; i++) {
            rsum[i] += __shfl_xor_sync(0xffffffffu, rsum[i], 1);
            rsum[i] += __shfl_xor_sync(0xffffffffu, rsum[i], 2);
        }
        if (t == 0) {
            atomicAdd(&Zs[rbase + g],      rsum[0]);
            atomicAdd(&Zs[rbase + 8 + g],  rsum[1]);
            atomicAdd(&Zs[rbase + 16 + g], rsum[2]);
            atomicAdd(&Zs[rbase + 24 + g], rsum[3]);
        }
        __syncthreads();

        // ---- write E tile fp16 to scratch ----
        size_t ebase = ((size_t)(h * BB + b) * NQ + q0) * NK + kt * 128;
#pragma unroll
        for (int j = 0; j < 4; j++) {
            int idx = tid + j * 256;
            int r = idx >> 4, c16 = idx & 15;
            uint4 v = *(uint4*)(Ph + r * PROW + c16 * 8);
            *(uint4*)((__half*)g_eh + ebase + (size_t)r * NK + c16 * 8) = v;
        }

        // ---- O += E @ V ----
        {
            int prow = ((lane >> 3) & 1) * 8 + (lane & 7);
            int pcol = (lane >> 4) * 8;
            int vrow = ((lane >> 3) & 1) * 8 + (lane & 7);
            int vcol = (lane >> 4) * 8;
#pragma unroll
            for (int kk = 0; kk < 8; kk++) {
                uint32_t a[2][4];
#pragma unroll
                for (int mt = 0; mt < 2; mt++)
                    ldsm_x4(a[mt],
                            pbase + ((rbase + mt * 16 + prow) * PROW + kk * 16 + pcol) * 2);
                uint32_t r4[4];
                ldsm_x4_t(r4, vb + ((kk * 16 + vrow) * VROW + wn * 16 + vcol) * 2);
                uint32_t bf[2][2];
                bf[0][0] = r4[0]; bf[0][1] = r4[1];
                bf[1][0] = r4[2]; bf[1][1] = r4[3];
#pragma unroll
                for (int mt = 0; mt < 2; mt++)
#pragma unroll
                    for (int nt = 0; nt < 2; nt++)
                        mma16(oacc[mt][nt], a[mt], bf[nt]);
            }
        }

        if (kt + 1 < NK / 128) cpa_wait0();
        __syncthreads();
    }

    // ---- write 1/Z ----
    if (tid < 64) {
        g_zi[(size_t)(b * HH + h) * NQ + q0 + tid] = 1.0f / Zs[tid];
    }

    // ---- stage O (disjoint), coalesced write to g_o ----
    float* Os = (float*)Ph;
#pragma unroll
    for (int mt = 0; mt < 2; mt++) {
        int r0 = rbase + mt * 16 + g, r1 = r0 + 8;
#pragma unroll
        for (int nt = 0; nt < 2; nt++) {
            int c0 = wn * 16 + nt * 8 + 2 * t;
            Os[r0 * 68 + c0]     = oacc[mt][nt][0];
            Os[r0 * 68 + c0 + 1] = oacc[mt][nt][1];
            Os[r1 * 68 + c0]     = oacc[mt][nt][2];
            Os[r1 * 68 + c0 + 1] = oacc[mt][nt][3];
        }
    }
    __syncthreads();
#pragma unroll
    for (int j = 0; j < 4; j++) {
        int idx = tid + j * 256;
        int r = idx >> 4, c = (idx & 15) * 4;
        float4 v;
        v.x = Os[r * 68 + c];
        v.y = Os[r * 68 + c + 1];
        v.z = Os[r * 68 + c + 2];
        v.w = Os[r * 68 + c + 3];
        *(float4*)(g_o + headbase + (size_t)(q0 + r) * DH + c) = v;
    }
}

// ============================================================
// Finalize attn: attn[a, :] = fp32(g_eh[a, :]) * (1/Z)
// ============================================================
__global__ __launch_bounds__(256) void norm_attn_kernel(float* __restrict__ attn)
{
    int a = blockIdx.x;                 // 0 .. 65535
    int hb = a >> 12;                   // h*BB + b
    int q  = a & 4095;
    int h = hb >> 1, b = hb & 1;
    float zi = g_zi[(size_t)(b * HH + h) * NQ + q];
    const uint4* src = (const uint4*)((const __half*)g_eh + (size_t)a * NK);
    float4* dst = (float4*)(attn + (size_t)a * NK);
    int i = threadIdx.x;
#pragma unroll
    for (int j = 0; j < 2; j++) {
        int idx = i + j * 256;
        uint4 hv = src[idx];
        __half2* hp = (__half2*)&hv;
        float2 f0 = __half22float2(hp[0]);
        float2 f1 = __half22float2(hp[1]);
        float2 f2 = __half22float2(hp[2]);
        float2 f3 = __half22float2(hp[3]);
        dst[idx * 2]     = make_float4(f0.x * zi, f0.y * zi, f1.x * zi, f1.y * zi);
        dst[idx * 2 + 1] = make_float4(f2.x * zi, f2.y * zi, f3.x * zi, f3.y * zi);
    }
}

// ============================================================
extern "C" void kernel_launch(void* const* d_in, const int* in_sizes, int n_in,
                              void* d_out, int out_size)
{
    const float* q  = (const float*)d_in[0];
    const float* k  = (const float*)d_in[1];
    const float* v  = (const float*)d_in[2];
    const unsigned char* mask = (const unsigned char*)d_in[3];
    const float* Wq = (const float*)d_in[4];
    const float* bq = (const float*)d_in[5];
    const float* Wk = (const float*)d_in[6];
    const float* bk = (const float*)d_in[7];
    const float* Wv = (const float*)d_in[8];
    const float* bv = (const float*)d_in[9];
    const float* Wo = (const float*)d_in[10];
    const float* bo = (const float*)d_in[11];

    float* out  = (float*)d_out;
    float* attn = out;                                    // [16, 4096, 4096]
    float* outp = out + (size_t)HH * BB * NQ * NK;        // [2, 4096, 512]

    mask_scan_kernel<<<dim3(BB * 64 * 32), 256>>>(mask);
    proj_qkv_kernel<<<dim3(64, 8, 3), 256>>>(q, k, v, Wq, Wk, Wv, bq, bk, bv);

    cudaFuncSetAttribute(attn_kernel, cudaFuncAttributeMaxDynamicSharedMemorySize, SMEM_BYTES);
    attn_kernel<<<dim3(NQ / 64, BB * HH), 256, SMEM_BYTES>>>(mask);

    norm_attn_kernel<<<dim3(HH * BB * NQ), 256>>>(attn);

    proj_out_kernel<<<dim3(64, 8), 256>>>(Wo, bo, outp);
}

// round 14
// speedup vs baseline: 1.4980x; 1.4980x over previous
#include <cuda_runtime.h>
#include <cuda_fp16.h>
#include <cstdint>

#define BB 2
#define HH 8
#define DH 64
#define DM 512
#define NQ 4096
#define NK 4096

// -------- scratch (no allocations allowed) --------
__device__ __half g_qh[BB*HH*NQ*DH];
__device__ __half g_kh[BB*HH*NK*DH];
__device__ __half g_vh[BB*HH*NK*DH];
__device__ float  g_o [BB*HH*NQ*DH];           // UNNORMALIZED O (E @ V)
__device__ float  g_zi[BB*HH*NQ];              // 1 / rowsum(exp(S))
__device__ __half g_eh[(size_t)BB*HH*NQ*NK];   // unnormalized E, fp16
__device__ unsigned char g_mflags[BB*64*32];   // per-(b,qtile,ktile) mask flag

__device__ __forceinline__ float to_tf32(float x) {
    float r;
    asm("cvt.rna.tf32.f32 %0, %1;" : "=f"(r) : "f"(x));
    return r;
}

// tf32: D += A(16x8) * B(8x8)
__device__ __forceinline__ void mma8(float* d, const float* a, const float* b) {
    asm("mma.sync.aligned.m16n8k8.row.col.f32.tf32.tf32.f32 "
        "{%0,%1,%2,%3}, {%4,%5,%6,%7}, {%8,%9}, {%0,%1,%2,%3};"
        : "+f"(d[0]), "+f"(d[1]), "+f"(d[2]), "+f"(d[3])
        : "r"(__float_as_uint(a[0])), "r"(__float_as_uint(a[1])),
          "r"(__float_as_uint(a[2])), "r"(__float_as_uint(a[3])),
          "r"(__float_as_uint(b[0])), "r"(__float_as_uint(b[1])));
}

// fp16: D(16x8,f32) += A(16x16) * B(16x8)
__device__ __forceinline__ void mma16(float* d, const uint32_t* a, const uint32_t* b) {
    asm("mma.sync.aligned.m16n8k16.row.col.f32.f16.f16.f32 "
        "{%0,%1,%2,%3}, {%4,%5,%6,%7}, {%8,%9}, {%0,%1,%2,%3};"
        : "+f"(d[0]), "+f"(d[1]), "+f"(d[2]), "+f"(d[3])
        : "r"(a[0]), "r"(a[1]), "r"(a[2]), "r"(a[3]),
          "r"(b[0]), "r"(b[1]));
}

__device__ __forceinline__ void ldsm_x4(uint32_t* r, uint32_t addr) {
    asm volatile("ldmatrix.sync.aligned.m8n8.x4.shared.b16 {%0,%1,%2,%3}, [%4];"
        : "=r"(r[0]), "=r"(r[1]), "=r"(r[2]), "=r"(r[3]) : "r"(addr));
}
__device__ __forceinline__ void ldsm_x4_t(uint32_t* r, uint32_t addr) {
    asm volatile("ldmatrix.sync.aligned.m8n8.x4.trans.shared.b16 {%0,%1,%2,%3}, [%4];"
        : "=r"(r[0]), "=r"(r[1]), "=r"(r[2]), "=r"(r[3]) : "r"(addr));
}

__device__ __forceinline__ void cpa16(uint32_t dst, const void* src) {
    asm volatile("cp.async.cg.shared.global [%0], [%1], 16;" :: "r"(dst), "l"(src));
}
__device__ __forceinline__ void cpa_commit() {
    asm volatile("cp.async.commit_group;" ::: "memory");
}
__device__ __forceinline__ void cpa_wait0() {
    asm volatile("cp.async.wait_group 0;" ::: "memory");
}

__device__ __forceinline__ uint32_t pack_h2(float x, float y) {
    __half2 h = __floats2half2_rn(x, y);
    return *(uint32_t*)&h;
}
__device__ __forceinline__ uint32_t smem_u32(const void* p) {
    return (uint32_t)__cvta_generic_to_shared(p);
}

// ============================================================
// Mask tile scan
// ============================================================
__global__ __launch_bounds__(256) void mask_scan_kernel(const unsigned char* __restrict__ mask)
{
    int bid = blockIdx.x;
    int b  = bid >> 11;
    int qt = (bid >> 5) & 63;
    int kt = bid & 31;
    const uint4* s = (const uint4*)(mask + (size_t)b * NQ * NK
                                    + (size_t)(qt * 64 + (threadIdx.x >> 2)) * NK
                                    + kt * 128 + (threadIdx.x & 3) * 32);
    uint4 a = s[0], c = s[1];
    unsigned v = a.x | a.y | a.z | a.w | c.x | c.y | c.z | c.w;
#pragma unroll
    for (int o = 16; o > 0; o >>= 1) v |= __shfl_xor_sync(0xffffffffu, v, o);
    __shared__ unsigned sflag;
    if (threadIdx.x == 0) sflag = 0u;
    __syncthreads();
    if ((threadIdx.x & 31) == 0 && v) atomicOr(&sflag, 1u);
    __syncthreads();
    if (threadIdx.x == 0) g_mflags[bid] = (unsigned char)(sflag != 0u);
}

// ============================================================
// QKV projection (tf32): Y = X @ W^T + bias -> fp16, head-major scatter.
// ============================================================
__global__ __launch_bounds__(256) void proj_head_kernel(
    const float* __restrict__ X, const float* __restrict__ W,
    const float* __restrict__ bias, int sel)
{
    __half* dst = sel == 0 ? g_qh : (sel == 1 ? g_kh : g_vh);
    __shared__ float As[128][36];
    __shared__ float Ws[64][36];
    int tid = threadIdx.x;
    int lane = tid & 31, warp = tid >> 5;
    int g = lane >> 2, t = lane & 3;
    int wm = warp >> 1, wn = warp & 1;
    int m0 = blockIdx.x * 128;
    int h  = blockIdx.y;

    float acc[2][4][4];
#pragma unroll
    for (int i = 0; i < 2; i++)
#pragma unroll
        for (int j = 0; j < 4; j++)
#pragma unroll
            for (int c = 0; c < 4; c++) acc[i][j][c] = 0.f;

    int rl = tid >> 3, cl = (tid & 7) * 4;
    for (int k0 = 0; k0 < DM; k0 += 32) {
#pragma unroll
        for (int i = 0; i < 4; i++) {
            int r = rl + i * 32;
            float4 v = *(const float4*)(X + (size_t)(m0 + r) * DM + k0 + cl);
            As[r][cl]   = to_tf32(v.x);
            As[r][cl+1] = to_tf32(v.y);
            As[r][cl+2] = to_tf32(v.z);
            As[r][cl+3] = to_tf32(v.w);
        }
#pragma unroll
        for (int i = 0; i < 2; i++) {
            int r = rl + i * 32;
            float4 v = *(const float4*)(W + (size_t)(h * 64 + r) * DM + k0 + cl);
            Ws[r][cl]   = to_tf32(v.x);
            Ws[r][cl+1] = to_tf32(v.y);
            Ws[r][cl+2] = to_tf32(v.z);
            Ws[r][cl+3] = to_tf32(v.w);
        }
        __syncthreads();
#pragma unroll
        for (int kk = 0; kk < 4; kk++) {
            float a[2][4];
#pragma unroll
            for (int mt = 0; mt < 2; mt++) {
                int rb = wm * 32 + mt * 16;
                a[mt][0] = As[rb + g][kk*8 + t];
                a[mt][1] = As[rb + 8 + g][kk*8 + t];
                a[mt][2] = As[rb + g][kk*8 + t + 4];
                a[mt][3] = As[rb + 8 + g][kk*8 + t + 4];
            }
            float bf[4][2];
#pragma unroll
            for (int nt = 0; nt < 4; nt++) {
                int nl = wn * 32 + nt * 8 + g;
                bf[nt][0] = Ws[nl][kk*8 + t];
                bf[nt][1] = Ws[nl][kk*8 + t + 4];
            }
#pragma unroll
            for (int mt = 0; mt < 2; mt++)
#pragma unroll
                for (int nt = 0; nt < 4; nt++)
                    mma8(acc[mt][nt], a[mt], bf[nt]);
        }
        __syncthreads();
    }
#pragma unroll
    for (int mt = 0; mt < 2; mt++) {
        int r0 = m0 + wm * 32 + mt * 16 + g;
        int r1 = r0 + 8;
#pragma unroll
        for (int nt = 0; nt < 4; nt++) {
            int col = wn * 32 + nt * 8 + 2 * t;
            float b0v = bias[h * 64 + col], b1v = bias[h * 64 + col + 1];
            int b_ = r0 >> 12, q_ = r0 & 4095;
            *(uint32_t*)(dst + (size_t)((b_ * HH + h) * NQ + q_) * DH + col) =
                pack_h2(acc[mt][nt][0] + b0v, acc[mt][nt][1] + b1v);
            b_ = r1 >> 12; q_ = r1 & 4095;
            *(uint32_t*)(dst + (size_t)((b_ * HH + h) * NQ + q_) * DH + col) =
                pack_h2(acc[mt][nt][2] + b0v, acc[mt][nt][3] + b1v);
        }
    }
}

// ============================================================
// Output projection (tf32): output = (concat_heads(g_o) * invZ) @ Wo^T + bo
// ============================================================
__global__ __launch_bounds__(256) void proj_out_kernel(
    const float* __restrict__ W, const float* __restrict__ bias,
    float* __restrict__ Y)
{
    __shared__ float As[128][36];
    __shared__ float Ws[64][36];
    int tid = threadIdx.x;
    int lane = tid & 31, warp = tid >> 5;
    int g = lane >> 2, t = lane & 3;
    int wm = warp >> 1, wn = warp & 1;
    int m0 = blockIdx.x * 128;
    int n0 = blockIdx.y * 64;

    float acc[2][4][4];
#pragma unroll
    for (int i = 0; i < 2; i++)
#pragma unroll
        for (int j = 0; j < 4; j++)
#pragma unroll
            for (int c = 0; c < 4; c++) acc[i][j][c] = 0.f;

    int rl = tid >> 3, cl = (tid & 7) * 4;
    for (int k0 = 0; k0 < DM; k0 += 32) {
        int head = k0 >> 6;
        int dd = (k0 & 63) + cl;
#pragma unroll
        for (int i = 0; i < 4; i++) {
            int r = rl + i * 32;
            int row = m0 + r;
            int b_ = row >> 12, q_ = row & 4095;
            size_t hb = (size_t)(b_ * HH + head) * NQ + q_;
            float zi = g_zi[hb];
            float4 v = *(const float4*)(g_o + hb * DH + dd);
            As[r][cl]   = to_tf32(v.x * zi);
            As[r][cl+1] = to_tf32(v.y * zi);
            As[r][cl+2] = to_tf32(v.z * zi);
            As[r][cl+3] = to_tf32(v.w * zi);
        }
#pragma unroll
        for (int i = 0; i < 2; i++) {
            int r = rl + i * 32;
            float4 v = *(const float4*)(W + (size_t)(n0 + r) * DM + k0 + cl);
            Ws[r][cl]   = to_tf32(v.x);
            Ws[r][cl+1] = to_tf32(v.y);
            Ws[r][cl+2] = to_tf32(v.z);
            Ws[r][cl+3] = to_tf32(v.w);
        }
        __syncthreads();
#pragma unroll
        for (int kk = 0; kk < 4; kk++) {
            float a[2][4];
#pragma unroll
            for (int mt = 0; mt < 2; mt++) {
                int rb = wm * 32 + mt * 16;
                a[mt][0] = As[rb + g][kk*8 + t];
                a[mt][1] = As[rb + 8 + g][kk*8 + t];
                a[mt][2] = As[rb + g][kk*8 + t + 4];
                a[mt][3] = As[rb + 8 + g][kk*8 + t + 4];
            }
            float bf[4][2];
#pragma unroll
            for (int nt = 0; nt < 4; nt++) {
                int nl = wn * 32 + nt * 8 + g;
                bf[nt][0] = Ws[nl][kk*8 + t];
                bf[nt][1] = Ws[nl][kk*8 + t + 4];
            }
#pragma unroll
            for (int mt = 0; mt < 2; mt++)
#pragma unroll
                for (int nt = 0; nt < 4; nt++)
                    mma8(acc[mt][nt], a[mt], bf[nt]);
        }
        __syncthreads();
    }
#pragma unroll
    for (int mt = 0; mt < 2; mt++) {
        int r0 = m0 + wm * 32 + mt * 16 + g;
        int r1 = r0 + 8;
#pragma unroll
        for (int nt = 0; nt < 4; nt++) {
            int col = wn * 32 + nt * 8 + 2 * t;
            float b0v = bias[n0 + col], b1v = bias[n0 + col + 1];
            float* p = Y + (size_t)r0 * DM + n0 + col;
            p[0] = acc[mt][nt][0] + b0v;
            p[1] = acc[mt][nt][1] + b1v;
            p = Y + (size_t)r1 * DM + n0 + col;
            p[0] = acc[mt][nt][2] + b0v;
            p[1] = acc[mt][nt][3] + b1v;
        }
    }
}

// ============================================================
// Attention: fp16 mma + ldmatrix + cp.async double-buffered K/V.
// (exact round-7 structure)
// ============================================================
#define QH_OFF   0                     // half [64][72]       =  9216
#define KH_OFF   9216                  // 2 x half [128][72]  = 36864
#define VH_OFF   46080                 // 2 x half [128][72]  = 36864
#define PH_OFF   82944                 // half [64][136]      = 17408 (also float Os[64][68])
#define ZS_OFF   100352                // float [64]
#define MS_OFF   100608                // u32 [64][32]        =  8192
#define SMEM_BYTES 108800

#define QROW 72
#define KROW 72
#define VROW 72
#define PROW 136
#define KBUF 18432
#define VBUF 18432

__global__ __launch_bounds__(256, 2) void attn_kernel(const unsigned char* __restrict__ mask)
{
    extern __shared__ char smraw[];
    __half* Qh = (__half*)(smraw + QH_OFF);
    __half* Ph = (__half*)(smraw + PH_OFF);
    float*  Zs = (float*)(smraw + ZS_OFF);
    unsigned int* Ms = (unsigned int*)(smraw + MS_OFF);
    uint32_t* Phw = (uint32_t*)Ph;

    int tid = threadIdx.x;
    int lane = tid & 31, warp = tid >> 5;
    int g = lane >> 2, t = lane & 3;
    int wm = warp >> 2;
    int wn = warp & 3;
    int q0 = blockIdx.x * 64;
    int bh = blockIdx.y;
    int b = bh >> 3, h = bh & 7;
    size_t headbase = (size_t)(b * HH + h) * NQ * DH;
    const unsigned char* mbase = mask + (size_t)(b * NQ + q0) * NK;
    int mfbase = b * 2048 + blockIdx.x * 32;
    int rbase = wm * 32;

    uint32_t qbase = smem_u32(Qh);
    uint32_t kbase = smem_u32(smraw + KH_OFF);
    uint32_t vbase = smem_u32(smraw + VH_OFF);
    uint32_t pbase = smem_u32(Ph);

    // ---- prologue: cp.async Q tile + K/V tile 0 ----
    {
#pragma unroll
        for (int j = 0; j < 2; j++) {
            int idx = tid + j * 256;
            int r = idx >> 3, o = (idx & 7) * 8;
            cpa16(qbase + (r * QROW + o) * 2, g_qh + headbase + (size_t)(q0 + r) * DH + o);
        }
#pragma unroll
        for (int j = 0; j < 4; j++) {
            int idx = tid + j * 256;
            int r = idx >> 3, o = (idx & 7) * 8;
            cpa16(kbase + (r * KROW + o) * 2, g_kh + headbase + (size_t)r * DH + o);
            cpa16(vbase + (r * VROW + o) * 2, g_vh + headbase + (size_t)r * DH + o);
        }
        cpa_commit();
    }
    if (tid < 64) Zs[tid] = 0.f;
    cpa_wait0();
    __syncthreads();

    // ---- hoist Q A-fragments ----
    uint32_t qa[2][4][4];
    {
        int qrow = ((lane >> 3) & 1) * 8 + (lane & 7);
        int qcol = (lane >> 4) * 8;
#pragma unroll
        for (int mt = 0; mt < 2; mt++)
#pragma unroll
            for (int kk = 0; kk < 4; kk++)
                ldsm_x4(qa[mt][kk],
                        qbase + ((rbase + mt * 16 + qrow) * QROW + kk * 16 + qcol) * 2);
    }

    float oacc[2][2][4];
#pragma unroll
    for (int i = 0; i < 2; i++)
#pragma unroll
        for (int j = 0; j < 2; j++)
#pragma unroll
            for (int c = 0; c < 4; c++) oacc[i][j][c] = 0.f;

    for (int kt = 0; kt < NK / 128; kt++) {
        int buf = kt & 1;
        uint32_t kb = kbase + buf * KBUF;
        uint32_t vb = vbase + buf * VBUF;
        unsigned char mflag = g_mflags[mfbase + kt];

        // ---- prefetch next K/V tile ----
        if (kt + 1 < NK / 128) {
            int nbuf = buf ^ 1;
            const __half* ksrc = g_kh + headbase + (size_t)(kt + 1) * 128 * DH;
            const __half* vsrc = g_vh + headbase + (size_t)(kt + 1) * 128 * DH;
#pragma unroll
            for (int j = 0; j < 4; j++) {
                int idx = tid + j * 256;
                int r = idx >> 3, o = (idx & 7) * 8;
                cpa16(kbase + nbuf * KBUF + (r * KROW + o) * 2, ksrc + (size_t)r * DH + o);
                cpa16(vbase + nbuf * VBUF + (r * VROW + o) * 2, vsrc + (size_t)r * DH + o);
            }
            cpa_commit();
        }

        if (mflag) {
            int r = tid >> 2, cb = (tid & 3) * 8;
            const uint4* src = (const uint4*)(mbase + (size_t)r * NK + kt * 128 + cb * 4);
            uint4 m0 = src[0], m1 = src[1];
            *(uint4*)(Ms + r * 32 + cb)     = m0;
            *(uint4*)(Ms + r * 32 + cb + 4) = m1;
            __syncthreads();
        }

        // ---- S = Q K^T ----
        float sacc[2][4][4];
#pragma unroll
        for (int i = 0; i < 2; i++)
#pragma unroll
            for (int j = 0; j < 4; j++)
#pragma unroll
                for (int c = 0; c < 4; c++) sacc[i][j][c] = 0.f;
        {
            int kn = (lane >> 4) * 8 + (lane & 7);
            int kc = ((lane >> 3) & 1) * 8;
#pragma unroll
            for (int kk = 0; kk < 4; kk++) {
                uint32_t bf[4][2];
#pragma unroll
                for (int half_n = 0; half_n < 2; half_n++) {
                    uint32_t r4[4];
                    ldsm_x4(r4, kb + ((wn * 32 + half_n * 16 + kn) * KROW + kk * 16 + kc) * 2);
                    bf[half_n * 2][0]     = r4[0];
                    bf[half_n * 2][1]     = r4[1];
                    bf[half_n * 2 + 1][0] = r4[2];
                    bf[half_n * 2 + 1][1] = r4[3];
                }
#pragma unroll
                for (int mt = 0; mt < 2; mt++)
#pragma unroll
                    for (int nt = 0; nt < 4; nt++)
                        mma16(sacc[mt][nt], qa[mt][kk], bf[nt]);
            }
        }

        // ---- E = exp(S/8); Z accumulate; stage fp16 ----
        const float SC = 0.125f;
        float rsum[4] = {0.f, 0.f, 0.f, 0.f};
        if (!mflag) {
#pragma unroll
            for (int mt = 0; mt < 2; mt++) {
                int r0 = rbase + mt * 16 + g, r1 = r0 + 8;
#pragma unroll
                for (int nt = 0; nt < 4; nt++) {
                    int c0 = wn * 32 + nt * 8 + 2 * t;
                    float p00 = __expf(sacc[mt][nt][0] * SC);
                    float p01 = __expf(sacc[mt][nt][1] * SC);
                    float p10 = __expf(sacc[mt][nt][2] * SC);
                    float p11 = __expf(sacc[mt][nt][3] * SC);
                    rsum[mt*2]     += p00 + p01;
                    rsum[mt*2 + 1] += p10 + p11;
                    Phw[r0 * 68 + (c0 >> 1)] = pack_h2(p00, p01);
                    Phw[r1 * 68 + (c0 >> 1)] = pack_h2(p10, p11);
                }
            }
        } else {
            const unsigned char* Mb = (const unsigned char*)Ms;
#pragma unroll
            for (int mt = 0; mt < 2; mt++) {
                int r0 = rbase + mt * 16 + g, r1 = r0 + 8;
#pragma unroll
                for (int nt = 0; nt < 4; nt++) {
                    int c0 = wn * 32 + nt * 8 + 2 * t;
                    float p00 = Mb[r0*128 + c0]     ? 0.f : __expf(sacc[mt][nt][0] * SC);
                    float p01 = Mb[r0*128 + c0 + 1] ? 0.f : __expf(sacc[mt][nt][1] * SC);
                    float p10 = Mb[r1*128 + c0]     ? 0.f : __expf(sacc[mt][nt][2] * SC);
                    float p11 = Mb[r1*128 + c0 + 1] ? 0.f : __expf(sacc[mt][nt][3] * SC);
                    rsum[mt*2]     += p00 + p01;
                    rsum[mt*2 + 1] += p10 + p11;
                    Phw[r0 * 68 + (c0 >> 1)] = pack_h2(p00, p01);
                    Phw[r1 * 68 + (c0 >> 1)] = pack_h2(p10, p11);
                }
            }
        }
#pragma unroll
        for (int i = 0; i < 4; i++) {
            rsum[i] += __shfl_xor_sync(0xffffffffu, rsum[i], 1);
            rsum[i] += __shfl_xor_sync(0xffffffffu, rsum[i], 2);
        }
        if (t == 0) {
            atomicAdd(&Zs[rbase + g],      rsum[0]);
            atomicAdd(&Zs[rbase + 8 + g],  rsum[1]);
            atomicAdd(&Zs[rbase + 16 + g], rsum[2]);
            atomicAdd(&Zs[rbase + 24 + g], rsum[3]);
        }
        __syncthreads();

        // ---- write E tile fp16 to scratch ----
        size_t ebase = ((size_t)(h * BB + b) * NQ + q0) * NK + kt * 128;
#pragma unroll
        for (int j = 0; j < 4; j++) {
            int idx = tid + j * 256;
            int r = idx >> 4, c16 = idx & 15;
            uint4 v = *(uint4*)(Ph + r * PROW + c16 * 8);
            *(uint4*)((__half*)g_eh + ebase + (size_t)r * NK + c16 * 8) = v;
        }

        // ---- O += E @ V ----
        {
            int prow = ((lane >> 3) & 1) * 8 + (lane & 7);
            int pcol = (lane >> 4) * 8;
            int vrow = ((lane >> 3) & 1) * 8 + (lane & 7);
            int vcol = (lane >> 4) * 8;
#pragma unroll
            for (int kk = 0; kk < 8; kk++) {
                uint32_t a[2][4];
#pragma unroll
                for (int mt = 0; mt < 2; mt++)
                    ldsm_x4(a[mt],
                            pbase + ((rbase + mt * 16 + prow) * PROW + kk * 16 + pcol) * 2);
                uint32_t r4[4];
                ldsm_x4_t(r4, vb + ((kk * 16 + vrow) * VROW + wn * 16 + vcol) * 2);
                uint32_t bf[2][2];
                bf[0][0] = r4[0]; bf[0][1] = r4[1];
                bf[1][0] = r4[2]; bf[1][1] = r4[3];
#pragma unroll
                for (int mt = 0; mt < 2; mt++)
#pragma unroll
                    for (int nt = 0; nt < 2; nt++)
                        mma16(oacc[mt][nt], a[mt], bf[nt]);
            }
        }

        if (kt + 1 < NK / 128) cpa_wait0();
        __syncthreads();
    }

    // ---- write 1/Z ----
    if (tid < 64) {
        g_zi[(size_t)(b * HH + h) * NQ + q0 + tid] = 1.0f / Zs[tid];
    }

    // ---- stage O (disjoint), coalesced write to g_o ----
    float* Os = (float*)Ph;
#pragma unroll
    for (int mt = 0; mt < 2; mt++) {
        int r0 = rbase + mt * 16 + g, r1 = r0 + 8;
#pragma unroll
        for (int nt = 0; nt < 2; nt++) {
            int c0 = wn * 16 + nt * 8 + 2 * t;
            Os[r0 * 68 + c0]     = oacc[mt][nt][0];
            Os[r0 * 68 + c0 + 1] = oacc[mt][nt][1];
            Os[r1 * 68 + c0]     = oacc[mt][nt][2];
            Os[r1 * 68 + c0 + 1] = oacc[mt][nt][3];
        }
    }
    __syncthreads();
#pragma unroll
    for (int j = 0; j < 4; j++) {
        int idx = tid + j * 256;
        int r = idx >> 4, c = (idx & 15) * 4;
        float4 v;
        v.x = Os[r * 68 + c];
        v.y = Os[r * 68 + c + 1];
        v.z = Os[r * 68 + c + 2];
        v.w = Os[r * 68 + c + 3];
        *(float4*)(g_o + headbase + (size_t)(q0 + r) * DH + c) = v;
    }
}

// ============================================================
// Finalize attn: attn[a, :] = fp32(g_eh[a, :]) * (1/Z)
// COALESCED: thread loads uint2 (4 halves) -> stores ONE float4 at same idx.
// ============================================================
__global__ __launch_bounds__(256) void norm_attn_kernel(float* __restrict__ attn)
{
    int a = blockIdx.x;                 // 0 .. 65535
    int hb = a >> 12;                   // h*BB + b
    int q  = a & 4095;
    int h = hb >> 1, b = hb & 1;
    float zi = g_zi[(size_t)(b * HH + h) * NQ + q];
    const uint2* src = (const uint2*)((const __half*)g_eh + (size_t)a * NK);
    float4* dst = (float4*)(attn + (size_t)a * NK);
    int i = threadIdx.x;
#pragma unroll
    for (int j = 0; j < 4; j++) {
        int idx = i + j * 256;          // 0..1023, coalesced on BOTH sides
        uint2 hv = src[idx];
        __half2* hp = (__half2*)&hv;
        float2 f0 = __half22float2(hp[0]);
        float2 f1 = __half22float2(hp[1]);
        dst[idx] = make_float4(f0.x * zi, f0.y * zi, f1.x * zi, f1.y * zi);
    }
}

// ============================================================
extern "C" void kernel_launch(void* const* d_in, const int* in_sizes, int n_in,
                              void* d_out, int out_size)
{
    const float* q  = (const float*)d_in[0];
    const float* k  = (const float*)d_in[1];
    const float* v  = (const float*)d_in[2];
    const unsigned char* mask = (const unsigned char*)d_in[3];
    const float* Wq = (const float*)d_in[4];
    const float* bq = (const float*)d_in[5];
    const float* Wk = (const float*)d_in[6];
    const float* bk = (const float*)d_in[7];
    const float* Wv = (const float*)d_in[8];
    const float* bv = (const float*)d_in[9];
    const float* Wo = (const float*)d_in[10];
    const float* bo = (const float*)d_in[11];

    float* out  = (float*)d_out;
    float* attn = out;                                    // [16, 4096, 4096]
    float* outp = out + (size_t)HH * BB * NQ * NK;        // [2, 4096, 512]

    mask_scan_kernel<<<dim3(BB * 64 * 32), 256>>>(mask);
    proj_head_kernel<<<dim3(64, 8), 256>>>(q, Wq, bq, 0);
    proj_head_kernel<<<dim3(64, 8), 256>>>(k, Wk, bk, 1);
    proj_head_kernel<<<dim3(64, 8), 256>>>(v, Wv, bv, 2);

    cudaFuncSetAttribute(attn_kernel, cudaFuncAttributeMaxDynamicSharedMemorySize, SMEM_BYTES);
    attn_kernel<<<dim3(NQ / 64, BB * HH), 256, SMEM_BYTES>>>(mask);

    norm_attn_kernel<<<dim3(HH * BB * NQ), 256>>>(attn);

    proj_out_kernel<<<dim3(64, 8), 256>>>(Wo, bo, outp);
}